// round 3
// baseline (speedup 1.0000x reference)
#include <cuda_runtime.h>

#define NN      51
#define HIDN    64
#define HEADS   4
#define DTOT    256     // HEADS*HIDN
#define OUTG    128
#define LH      32
#define NC      8
#define BBATCH  256
#define FFEAT   50
#define GG      (BBATCH*FFEAT)   // 12800
#define SLOPEF  0.01f
#define WPB     8                // warps (graphs) per gat block
#define GPB     64               // graphs per xp-gemm block

// ---------------- scratch (no allocs allowed) ----------------
__device__ float  d_u[HEADS * 4];        // usrc0, usrc1, udst0, udst1 per head
__device__ float4 d_vcomb[DTOT];         // (vs, vd, wbar, 0) per feature dim
__device__ float  d_WihT0[NN * OUTG];    // transposed Wih0: [n][gate]
__device__ float  d_b0[OUTG];
__device__ float  d_b1[OUTG];
__device__ float  d_ext[GG * NN];        // extracted rows
__device__ float  d_xp0[GG * OUTG];      // LSTM layer0 gate pre-activations
__device__ float  d_hseq[GG * LH];       // layer1 hidden outputs

// ---------------- helpers ----------------
__device__ __forceinline__ float fsig(float x) {
    return 1.0f / (1.0f + __expf(-x));
}
__device__ __forceinline__ float ftanhf(float x) {
    float e = __expf(-2.0f * fabsf(x));
    float r = __fdividef(1.0f - e, 1.0f + e);
    return copysignf(r, x);
}

// ---------------- kernel A: tiny precompute ----------------
__global__ void prep_kernel(const float* __restrict__ W1, const float* __restrict__ a1,
                            const float* __restrict__ W2, const float* __restrict__ a2,
                            const float* __restrict__ Wih0,
                            const float* __restrict__ bih0, const float* __restrict__ bhh0,
                            const float* __restrict__ bih1, const float* __restrict__ bhh1) {
    int t = threadIdx.x; // 256 threads
    // v_src, v_dst, w2bar  (thread t = feature dim d)
    {
        float vs = 0.f, vd = 0.f, wb = 0.f;
        for (int o = 0; o < OUTG; o++) {
            float w = W2[o * DTOT + t];
            vs += w * a2[o];
            vd += w * a2[OUTG + o];
            wb += w;
        }
        d_vcomb[t] = make_float4(vs, vd, wb * (1.0f / OUTG), 0.f);
    }
    // u[h][which]: which = side*2 + c   (side 0 = src, 1 = dst)
    if (t < HEADS * 4) {
        int h = t >> 2, which = t & 3;
        int c = which & 1, side = which >> 1;
        float s = 0.f;
        for (int o = 0; o < HIDN; o++)
            s += W1[(h * HIDN + o) * 2 + c] * a1[h * 2 * HIDN + side * HIDN + o];
        d_u[t] = s;
    }
    // transpose Wih0 -> [n][gate]
    for (int idx = t; idx < NN * OUTG; idx += 256) {
        int n = idx / OUTG, g = idx % OUTG;
        d_WihT0[idx] = Wih0[g * NN + n];
    }
    if (t < OUTG) {
        d_b0[t] = bih0[t] + bhh0[t];
        d_b1[t] = bih1[t] + bhh1[t];
    }
}

// ---------------- kernel B: fused GAT, warp-per-graph ----------------
__global__ void __launch_bounds__(256) gat_kernel(const float* __restrict__ feat,
                                                  const float* __restrict__ W1g) {
    __shared__ float2 W1s[DTOT];             // (w0,w1) per dim
    __shared__ float4 vcomb[DTOT];           // (vs,vd,wb,_)
    __shared__ float  us[HEADS * 4];
    __shared__ float2 xv[WPB][NN];           // node features per graph
    __shared__ float2 PR[WPB][HEADS][NN];    // exp(es), exp(.01 es)
    __shared__ float2 ssm[WPB][HEADS][NN];   // attention-weighted s0, s1
    __shared__ float4 P2z[WPB][NN];          // exp(es2), exp(.01es2), zbar, _
    __shared__ float2 Q2[WPB][NN];           // exp(ed2), exp(.01 ed2)

    int t = threadIdx.x, w = t >> 5, lane = t & 31;
    int g = blockIdx.x * WPB + w;

    // ---- loads ----
    if (t < DTOT) { W1s[t] = ((const float2*)W1g)[t]; vcomb[t] = d_vcomb[t]; }
    if (t < 16) us[t] = d_u[t];
    {
        const float2* x2 = (const float2*)feat + (size_t)g * NN;
        for (int i = lane; i < NN; i += 32) xv[w][i] = x2[i];
    }
    __syncthreads();

    // ---- stage 1: GAT1 logits + exps; keep own-edge-dst exps in regs ----
    float2 q[HEADS][2];
#pragma unroll
    for (int h = 0; h < HEADS; h++) {
        float u0 = us[h * 4 + 0], u1 = us[h * 4 + 1], u2 = us[h * 4 + 2], u3 = us[h * 4 + 3];
#pragma unroll
        for (int jb = 0; jb < 2; jb++) {
            int j = jb * 32 + lane;
            float2 xn = (j < NN) ? xv[w][j] : make_float2(0.f, 0.f);
            float es = xn.x * u0 + xn.y * u1;
            float ed = xn.x * u2 + xn.y * u3;
            if (j < NN) PR[w][h][j] = make_float2(__expf(es), __expf(SLOPEF * es));
            q[h][jb] = make_float2(__expf(ed), __expf(SLOPEF * ed));
        }
    }
    __syncwarp();

    // ---- stage 2: GAT1 attention-weighted feature sums (dual-j fused loop) ----
#pragma unroll
    for (int h = 0; h < HEADS; h++) {
        float2 q0 = q[h][0], q1 = q[h][1];
        float den0 = 0.f, s00 = 0.f, s01 = 0.f;
        float den1 = 0.f, s10 = 0.f, s11 = 0.f;
#pragma unroll 3
        for (int i = 0; i < NN; i++) {
            float2 pr = PR[w][h][i];
            float2 xi = xv[w][i];
            float w0 = fmaxf(pr.x * q0.x, pr.y * q0.y);
            float w1 = fmaxf(pr.x * q1.x, pr.y * q1.y);
            den0 += w0; s00 += w0 * xi.x; s01 += w0 * xi.y;
            den1 += w1; s10 += w1 * xi.x; s11 += w1 * xi.y;
        }
        {   // diag removal j0 = lane
            int j0 = lane;
            float2 pr = PR[w][h][j0]; float2 xj = xv[w][j0];
            float w0 = fmaxf(pr.x * q0.x, pr.y * q0.y);
            den0 -= w0; s00 -= w0 * xj.x; s01 -= w0 * xj.y;
            float inv = __fdividef(1.0f, den0);
            ssm[w][h][j0] = make_float2(s00 * inv, s01 * inv);
        }
        int j1 = 32 + lane;
        if (j1 < NN) {
            float2 pr = PR[w][h][j1]; float2 xj = xv[w][j1];
            float w1 = fmaxf(pr.x * q1.x, pr.y * q1.y);
            den1 -= w1; s10 -= w1 * xj.x; s11 -= w1 * xj.y;
            float inv = __fdividef(1.0f, den1);
            ssm[w][h][j1] = make_float2(s10 * inv, s11 * inv);
        }
    }
    __syncwarp();

    // ---- stage 3: elu(h1) projections -> es2, ed2, zbar (8-lane groups, 4 j/pass) ----
    {
        int grp = lane >> 3, gl = lane & 7;
#pragma unroll 1
        for (int p = 0; p < 13; p++) {
            int j = p * 4 + grp;
            bool valid = (j < NN);
            int jc = valid ? j : 0;
            float2 sh[HEADS];
#pragma unroll
            for (int h = 0; h < HEADS; h++) sh[h] = ssm[w][h][jc];
            float a_es = 0.f, a_ed = 0.f, a_zb = 0.f;
#pragma unroll
            for (int h = 0; h < HEADS; h++) {
                float sx = sh[h].x, sy = sh[h].y;
#pragma unroll
                for (int kk = 0; kk < 8; kk++) {
                    int d = h * 64 + kk * 8 + gl;
                    float2 wv = W1s[d];
                    float h1 = sx * wv.x + sy * wv.y;
                    float he = (h1 > 0.f) ? h1 : (__expf(h1) - 1.0f);
                    float4 vc = vcomb[d];
                    a_es += he * vc.x; a_ed += he * vc.y; a_zb += he * vc.z;
                }
            }
#pragma unroll
            for (int off = 4; off; off >>= 1) {
                a_es += __shfl_down_sync(0xffffffffu, a_es, off);
                a_ed += __shfl_down_sync(0xffffffffu, a_ed, off);
                a_zb += __shfl_down_sync(0xffffffffu, a_zb, off);
            }
            if (gl == 0 && valid) {
                P2z[w][j] = make_float4(__expf(a_es), __expf(SLOPEF * a_es), a_zb, 0.f);
                Q2[w][j] = make_float2(__expf(a_ed), __expf(SLOPEF * a_ed));
            }
        }
    }
    __syncwarp();

    // ---- stage 5: GAT2 attention -> extracted ----
    float* extg = d_ext + (size_t)g * NN;
#pragma unroll
    for (int jb = 0; jb < 2; jb++) {
        int j = jb * 32 + lane;
        if (j < NN) {
            float2 qq = Q2[w][j];
            float den = 0.f, acc = 0.f;
#pragma unroll 3
            for (int i = 0; i < NN; i++) {
                float4 p = P2z[w][i];
                float w_ = fmaxf(p.x * qq.x, p.y * qq.y);
                den += w_; acc += w_ * p.z;
            }
            float4 p = P2z[w][j];
            float w_ = fmaxf(p.x * qq.x, p.y * qq.y);
            den -= w_; acc -= w_ * p.z;
            extg[j] = acc * __fdividef(1.0f, den);
        }
    }
}

// ---------------- kernel B2: xp0 = ext @ WihT0 + b0 (tiled GEMM) ----------------
__global__ void __launch_bounds__(256) xp_kernel() {
    __shared__ float Wt[NN * OUTG];   // [n][col]
    __shared__ float b0s[OUTG];
    __shared__ float exts[GPB][NN];
    int t = threadIdx.x;
    int g0 = blockIdx.x * GPB;
    for (int i = t; i < NN * OUTG; i += 256) Wt[i] = d_WihT0[i];
    if (t < OUTG) b0s[t] = d_b0[t];
    for (int i = t; i < GPB * NN; i += 256) (&exts[0][0])[i] = d_ext[(size_t)g0 * NN + i];
    __syncthreads();

    int col = t & 127, half = t >> 7;
    float bb = b0s[col];
#pragma unroll
    for (int b8 = 0; b8 < 4; b8++) {
        int gbase = half * 32 + b8 * 8;
        float acc[8];
#pragma unroll
        for (int r = 0; r < 8; r++) acc[r] = bb;
#pragma unroll 3
        for (int n = 0; n < NN; n++) {
            float wv = Wt[n * OUTG + col];
#pragma unroll
            for (int r = 0; r < 8; r++) acc[r] += exts[gbase + r][n] * wv;
        }
#pragma unroll
        for (int r = 0; r < 8; r++)
            d_xp0[(size_t)(g0 + gbase + r) * OUTG + col] = acc[r];
    }
}

// ---------------- kernel C: pipelined 2-layer LSTM recurrence ----------------
__global__ void __launch_bounds__(256) lstm_kernel(const float* __restrict__ Whh0,
                                                   const float* __restrict__ Wih1,
                                                   const float* __restrict__ Whh1) {
    __shared__ float h0[LH], h1s[LH], g0[OUTG], g1[OUTG];
    int f = blockIdx.x;    // 50 blocks
    int t = threadIdx.x;   // 256 threads

    float wa[32], wbv[32];
    if (t < OUTG) {
#pragma unroll
        for (int k = 0; k < 32; k++) wa[k] = Whh0[t * 32 + k];
    } else {
        int r = t - OUTG;
#pragma unroll
        for (int k = 0; k < 32; k++) { wa[k] = Wih1[r * 32 + k]; wbv[k] = Whh1[r * 32 + k]; }
    }
    float b1v = (t >= OUTG) ? d_b1[t - OUTG] : 0.f;
    float c_ = 0.f;
    if (t < LH) { h0[t] = 0.f; h1s[t] = 0.f; }
    float xnext = (t < OUTG) ? d_xp0[(size_t)f * OUTG + t] : 0.f;  // timestep 0
    __syncthreads();

    for (int k = 0; k <= BBATCH; k++) {
        // phase A: gate pre-activations (layer0 @ time k, layer1 @ time k-1)
        if (t < OUTG) {
            if (k < BBATCH) {
                float xp = xnext;
                if (k + 1 < BBATCH)
                    xnext = d_xp0[((size_t)(k + 1) * FFEAT + f) * OUTG + t];
                const float4* h4 = (const float4*)h0;
                float a0 = 0.f, a1_ = 0.f, a2_ = 0.f, a3 = 0.f;
#pragma unroll
                for (int jj = 0; jj < 8; jj++) {
                    float4 hv = h4[jj];
                    a0 += wa[4 * jj] * hv.x;
                    a1_ += wa[4 * jj + 1] * hv.y;
                    a2_ += wa[4 * jj + 2] * hv.z;
                    a3 += wa[4 * jj + 3] * hv.w;
                }
                g0[t] = xp + ((a0 + a1_) + (a2_ + a3));
            }
        } else if (k >= 1) {
            int r = t - OUTG;
            const float4* h4 = (const float4*)h0;
            const float4* h14 = (const float4*)h1s;
            float a0 = 0.f, a1_ = 0.f, a2_ = 0.f, a3 = 0.f;
#pragma unroll
            for (int jj = 0; jj < 8; jj++) {
                float4 hv = h4[jj]; float4 hw = h14[jj];
                a0 += wa[4 * jj] * hv.x + wbv[4 * jj] * hw.x;
                a1_ += wa[4 * jj + 1] * hv.y + wbv[4 * jj + 1] * hw.y;
                a2_ += wa[4 * jj + 2] * hv.z + wbv[4 * jj + 2] * hw.z;
                a3 += wa[4 * jj + 3] * hv.w + wbv[4 * jj + 3] * hw.w;
            }
            g1[r] = b1v + ((a0 + a1_) + (a2_ + a3));
        }
        __syncthreads();
        // phase B: state updates
        if (t < 32) {
            if (k < BBATCH) {
                float gi = g0[t], gf = g0[32 + t], gg = g0[64 + t], go = g0[96 + t];
                c_ = fsig(gf) * c_ + fsig(gi) * ftanhf(gg);
                h0[t] = fsig(go) * ftanhf(c_);
            }
        } else if (t < 64 && k >= 1) {
            int r = t - 32;
            float gi = g1[r], gf = g1[32 + r], gg = g1[64 + r], go = g1[96 + r];
            c_ = fsig(gf) * c_ + fsig(gi) * ftanhf(gg);
            float hn = fsig(go) * ftanhf(c_);
            h1s[r] = hn;
            d_hseq[(((size_t)(k - 1)) * FFEAT + f) * LH + r] = hn;
        }
        __syncthreads();
    }
}

// ---------------- kernel D: final FC ----------------
__global__ void __launch_bounds__(256) fc_kernel(const float* __restrict__ Wfc,
                                                 const float* __restrict__ bfc,
                                                 float* __restrict__ out) {
    int b = blockIdx.x;          // 256 blocks
    int t = threadIdx.x;
    int k = t >> 5, lane = t & 31;   // 8 warps = 8 classes
    const float* y = d_hseq + (size_t)b * (FFEAT * LH);
    const float* w = Wfc + (size_t)k * (FFEAT * LH);
    float acc = 0.f;
    for (int i = lane; i < FFEAT * LH; i += 32)
        acc += y[i] * w[i];
#pragma unroll
    for (int off = 16; off; off >>= 1)
        acc += __shfl_down_sync(0xffffffffu, acc, off);
    if (lane == 0) out[b * NC + k] = acc + bfc[k];
}

// ---------------- launch ----------------
extern "C" void kernel_launch(void* const* d_in, const int* in_sizes, int n_in,
                              void* d_out, int out_size) {
    const float* feat = (const float*)d_in[0];
    const float* W1   = (const float*)d_in[1];
    const float* a1   = (const float*)d_in[2];
    const float* W2   = (const float*)d_in[3];
    const float* a2   = (const float*)d_in[4];
    const float* Wih0 = (const float*)d_in[5];
    const float* Whh0 = (const float*)d_in[6];
    const float* bih0 = (const float*)d_in[7];
    const float* bhh0 = (const float*)d_in[8];
    const float* Wih1 = (const float*)d_in[9];
    const float* Whh1 = (const float*)d_in[10];
    const float* bih1 = (const float*)d_in[11];
    const float* bhh1 = (const float*)d_in[12];
    const float* Wfc  = (const float*)d_in[13];
    const float* bfc  = (const float*)d_in[14];
    float* out = (float*)d_out;

    prep_kernel<<<1, 256>>>(W1, a1, W2, a2, Wih0, bih0, bhh0, bih1, bhh1);
    gat_kernel<<<GG / WPB, 256>>>(feat, W1);
    xp_kernel<<<GG / GPB, 256>>>();
    lstm_kernel<<<FFEAT, 256>>>(Whh0, Wih1, Whh1);
    fc_kernel<<<BBATCH, 256>>>(Wfc, bfc, out);
}

// round 4
// speedup vs baseline: 1.1475x; 1.1475x over previous
#include <cuda_runtime.h>

#define NN      51
#define HIDN    64
#define HEADS   4
#define DTOT    256     // HEADS*HIDN
#define OUTG    128
#define LH      32
#define NC      8
#define BBATCH  256
#define FFEAT   50
#define GG      (BBATCH*FFEAT)   // 12800
#define SLOPEF  0.01f
#define WPB     8                // warps (graphs) per gat block
#define LSTMB   FFEAT            // lstm blocks (first in grid)

// ---------------- scratch (no allocs allowed) ----------------
__device__ float  d_u[16];               // per-head (usrc0,usrc1,udst0,udst1)
__device__ float4 d_vcomb[DTOT];         // (vs, vd, wbar, 0)
__device__ float  d_WihT0[NN * OUTG];    // transposed Wih0: [n][gate]
__device__ float  d_b0[OUTG];
__device__ float  d_b1[OUTG];
__device__ float  d_ext[GG * NN];        // extracted rows
__device__ float  d_hseq[GG * LH];       // layer1 hidden outputs
__device__ int    d_cnt[BBATCH];         // per-batch-step completion counters

// ---------------- helpers ----------------
__device__ __forceinline__ float fsig(float x) {
    return 1.0f / (1.0f + __expf(-x));
}
__device__ __forceinline__ float ftanhf(float x) {
    float e = __expf(-2.0f * fabsf(x));
    float r = __fdividef(1.0f - e, 1.0f + e);
    return copysignf(r, x);
}

// ---------------- shared-memory overlays ----------------
struct __align__(16) GatSm {
    float2 W1s[DTOT];
    float4 vcomb[DTOT];
    float  us[16];
    float2 xv[WPB][NN];
    float2 PR[WPB][HEADS][NN];
    float2 ssm[WPB][HEADS][NN];
    float4 P2z[WPB][NN];
    float2 Q2[WPB][NN];
};
struct __align__(16) LstmSm {
    float Wt[NN * OUTG];                 // WihT0 tile
    __align__(16) float h0[LH];
    __align__(16) float h1s[LH];
    __align__(16) float g0[OUTG];
    __align__(16) float g1[OUTG];
    __align__(16) float xp[OUTG];        // input projection for next step
    __align__(16) float extn[2][56];     // double-buffered ext rows
    __align__(16) float b0s[OUTG];
};

// ---------------- kernel A: tiny precompute ----------------
__global__ void prep_kernel(const float* __restrict__ W1, const float* __restrict__ a1,
                            const float* __restrict__ W2, const float* __restrict__ a2,
                            const float* __restrict__ Wih0,
                            const float* __restrict__ bih0, const float* __restrict__ bhh0,
                            const float* __restrict__ bih1, const float* __restrict__ bhh1) {
    int t = threadIdx.x; // 256 threads
    {
        float vs = 0.f, vd = 0.f, wb = 0.f;
        for (int o = 0; o < OUTG; o++) {
            float w = W2[o * DTOT + t];
            vs += w * a2[o];
            vd += w * a2[OUTG + o];
            wb += w;
        }
        d_vcomb[t] = make_float4(vs, vd, wb * (1.0f / OUTG), 0.f);
    }
    if (t < 16) {
        int h = t >> 2, which = t & 3;
        int c = which & 1, side = which >> 1;
        float s = 0.f;
        for (int o = 0; o < HIDN; o++)
            s += W1[(h * HIDN + o) * 2 + c] * a1[h * 2 * HIDN + side * HIDN + o];
        d_u[t] = s;
    }
    for (int idx = t; idx < NN * OUTG; idx += 256) {
        int n = idx / OUTG, g = idx % OUTG;
        d_WihT0[idx] = Wih0[g * NN + n];
    }
    if (t < OUTG) {
        d_b0[t] = bih0[t] + bhh0[t];
        d_b1[t] = bih1[t] + bhh1[t];
    }
    if (t < BBATCH) d_cnt[t] = 0;   // reset progress counters each launch/replay
}

// ---------------- xp dot: S->xp[col] = b0[col] + ext . WihT0[:,col] ----------------
__device__ __forceinline__ void xp_dot(LstmSm* S, int buf, int col) {
    const float* wt = S->Wt + col;
    const float* ex = S->extn[buf];
    float a0 = S->b0s[col], a1 = 0.f, a2 = 0.f, a3 = 0.f;
#pragma unroll
    for (int n = 0; n < 48; n += 4) {
        float4 e = *(const float4*)(ex + n);
        a0 += e.x * wt[n * OUTG];
        a1 += e.y * wt[(n + 1) * OUTG];
        a2 += e.z * wt[(n + 2) * OUTG];
        a3 += e.w * wt[(n + 3) * OUTG];
    }
    a0 += ex[48] * wt[48 * OUTG];
    a1 += ex[49] * wt[49 * OUTG];
    a2 += ex[50] * wt[50 * OUTG];
    S->xp[col] = (a0 + a1) + (a2 + a3);
}

// ---------------- GAT role (blocks >= LSTMB) ----------------
__device__ __forceinline__ void gat_role(GatSm* S, const float* __restrict__ feat,
                                         const float* __restrict__ W1g, int gb) {
    int t = threadIdx.x, w = t >> 5, lane = t & 31;
    int g = gb * WPB + w;

    if (t < DTOT) { S->W1s[t] = ((const float2*)W1g)[t]; S->vcomb[t] = d_vcomb[t]; }
    if (t < 16) S->us[t] = d_u[t];
    {
        const float2* x2 = (const float2*)feat + (size_t)g * NN;
        for (int i = lane; i < NN; i += 32) S->xv[w][i] = x2[i];
    }
    __syncthreads();

    // stage 1: GAT1 logits + exps
    float2 q[HEADS][2];
#pragma unroll
    for (int h = 0; h < HEADS; h++) {
        float u0 = S->us[h * 4 + 0], u1 = S->us[h * 4 + 1];
        float u2 = S->us[h * 4 + 2], u3 = S->us[h * 4 + 3];
#pragma unroll
        for (int jb = 0; jb < 2; jb++) {
            int j = jb * 32 + lane;
            float2 xn = (j < NN) ? S->xv[w][j] : make_float2(0.f, 0.f);
            float es = xn.x * u0 + xn.y * u1;
            float ed = xn.x * u2 + xn.y * u3;
            if (j < NN) S->PR[w][h][j] = make_float2(__expf(es), __expf(SLOPEF * es));
            q[h][jb] = make_float2(__expf(ed), __expf(SLOPEF * ed));
        }
    }
    __syncwarp();

    // stage 2: attention-weighted feature sums
#pragma unroll
    for (int h = 0; h < HEADS; h++) {
        float2 q0 = q[h][0], q1 = q[h][1];
        float den0 = 0.f, s00 = 0.f, s01 = 0.f;
        float den1 = 0.f, s10 = 0.f, s11 = 0.f;
#pragma unroll 3
        for (int i = 0; i < NN; i++) {
            float2 pr = S->PR[w][h][i];
            float2 xi = S->xv[w][i];
            float w0 = fmaxf(pr.x * q0.x, pr.y * q0.y);
            float w1 = fmaxf(pr.x * q1.x, pr.y * q1.y);
            den0 += w0; s00 += w0 * xi.x; s01 += w0 * xi.y;
            den1 += w1; s10 += w1 * xi.x; s11 += w1 * xi.y;
        }
        {
            int j0 = lane;
            float2 pr = S->PR[w][h][j0]; float2 xj = S->xv[w][j0];
            float w0 = fmaxf(pr.x * q0.x, pr.y * q0.y);
            den0 -= w0; s00 -= w0 * xj.x; s01 -= w0 * xj.y;
            float inv = __fdividef(1.0f, den0);
            S->ssm[w][h][j0] = make_float2(s00 * inv, s01 * inv);
        }
        int j1 = 32 + lane;
        if (j1 < NN) {
            float2 pr = S->PR[w][h][j1]; float2 xj = S->xv[w][j1];
            float w1 = fmaxf(pr.x * q1.x, pr.y * q1.y);
            den1 -= w1; s10 -= w1 * xj.x; s11 -= w1 * xj.y;
            float inv = __fdividef(1.0f, den1);
            S->ssm[w][h][j1] = make_float2(s10 * inv, s11 * inv);
        }
    }
    __syncwarp();

    // stage 3: elu(h1) projections -> es2, ed2, zbar
    {
        int grp = lane >> 3, gl = lane & 7;
#pragma unroll 1
        for (int p = 0; p < 13; p++) {
            int j = p * 4 + grp;
            bool valid = (j < NN);
            int jc = valid ? j : 0;
            float2 sh[HEADS];
#pragma unroll
            for (int h = 0; h < HEADS; h++) sh[h] = S->ssm[w][h][jc];
            float a_es = 0.f, a_ed = 0.f, a_zb = 0.f;
#pragma unroll
            for (int h = 0; h < HEADS; h++) {
                float sx = sh[h].x, sy = sh[h].y;
#pragma unroll
                for (int kk = 0; kk < 8; kk++) {
                    int d = h * 64 + kk * 8 + gl;
                    float2 wv = S->W1s[d];
                    float h1 = sx * wv.x + sy * wv.y;
                    float he = (h1 > 0.f) ? h1 : (__expf(h1) - 1.0f);
                    float4 vc = S->vcomb[d];
                    a_es += he * vc.x; a_ed += he * vc.y; a_zb += he * vc.z;
                }
            }
#pragma unroll
            for (int off = 4; off; off >>= 1) {
                a_es += __shfl_down_sync(0xffffffffu, a_es, off);
                a_ed += __shfl_down_sync(0xffffffffu, a_ed, off);
                a_zb += __shfl_down_sync(0xffffffffu, a_zb, off);
            }
            if (gl == 0 && valid) {
                S->P2z[w][j] = make_float4(__expf(a_es), __expf(SLOPEF * a_es), a_zb, 0.f);
                S->Q2[w][j] = make_float2(__expf(a_ed), __expf(SLOPEF * a_ed));
            }
        }
    }
    __syncwarp();

    // stage 5: GAT2 attention -> extracted
    float* extg = d_ext + (size_t)g * NN;
#pragma unroll
    for (int jb = 0; jb < 2; jb++) {
        int j = jb * 32 + lane;
        if (j < NN) {
            float2 qq = S->Q2[w][j];
            float den = 0.f, acc = 0.f;
#pragma unroll 3
            for (int i = 0; i < NN; i++) {
                float4 p = S->P2z[w][i];
                float w_ = fmaxf(p.x * qq.x, p.y * qq.y);
                den += w_; acc += w_ * p.z;
            }
            float4 p = S->P2z[w][j];
            float w_ = fmaxf(p.x * qq.x, p.y * qq.y);
            den -= w_; acc -= w_ * p.z;
            extg[j] = acc * __fdividef(1.0f, den);
        }
    }
    // publish: graph g's ext row is complete
    __threadfence();
    if (lane == 0) atomicAdd(&d_cnt[g / FFEAT], 1);
}

// ---------------- LSTM role (blocks < LSTMB) ----------------
__device__ __forceinline__ void lstm_role(LstmSm* S,
                                          const float* __restrict__ Whh0,
                                          const float* __restrict__ Wih1,
                                          const float* __restrict__ Whh1) {
    int f = blockIdx.x;
    int t = threadIdx.x;

    for (int i = t; i < NN * OUTG; i += 256) S->Wt[i] = d_WihT0[i];
    if (t < OUTG) S->b0s[t] = d_b0[t];

    float wa[32], wbv[32];
    if (t < OUTG) {
#pragma unroll
        for (int k = 0; k < 32; k++) wa[k] = Whh0[t * 32 + k];
    } else {
        int r = t - OUTG;
#pragma unroll
        for (int k = 0; k < 32; k++) { wa[k] = Wih1[r * 32 + k]; wbv[k] = Whh1[r * 32 + k]; }
    }
    float b1v = (t >= OUTG) ? d_b1[t - OUTG] : 0.f;
    float c_ = 0.f;
    if (t < LH) { S->h0[t] = 0.f; S->h1s[t] = 0.f; }
    volatile int* vcnt = d_cnt;
    __syncthreads();

    // prologue: fetch ext rows for steps 0 and 1, build xp for step 0
    if (t < NN) {
        while (vcnt[0] < FFEAT) __nanosleep(200);
        __threadfence();
        S->extn[0][t] = __ldcg(&d_ext[(size_t)f * NN + t]);
        while (vcnt[1] < FFEAT) __nanosleep(200);
        __threadfence();
        S->extn[1][t] = __ldcg(&d_ext[((size_t)FFEAT + f) * NN + t]);
    }
    __syncthreads();
    if (t >= 64 && t < 192) xp_dot(S, 0, t - 64);
    __syncthreads();

    int cpre = 0;
    for (int k = 0; k <= BBATCH; k++) {
        // ---- phase A: gate dots (layer0 @ k, layer1 @ k-1), counter pre-read ----
        if (t < OUTG) {
            if (k < BBATCH) {
                const float4* h4 = (const float4*)S->h0;
                float xpv = S->xp[t];
                float a0 = 0.f, a1_ = 0.f, a2_ = 0.f, a3 = 0.f;
#pragma unroll
                for (int jj = 0; jj < 8; jj++) {
                    float4 hv = h4[jj];
                    a0 += wa[4 * jj] * hv.x;
                    a1_ += wa[4 * jj + 1] * hv.y;
                    a2_ += wa[4 * jj + 2] * hv.z;
                    a3 += wa[4 * jj + 3] * hv.w;
                }
                S->g0[t] = xpv + ((a0 + a1_) + (a2_ + a3));
            }
        } else {
            if (k >= 1) {
                int r = t - OUTG;
                const float4* h4 = (const float4*)S->h0;
                const float4* h14 = (const float4*)S->h1s;
                float a0 = 0.f, a1_ = 0.f, a2_ = 0.f, a3 = 0.f;
#pragma unroll
                for (int jj = 0; jj < 8; jj++) {
                    float4 hv = h4[jj]; float4 hw = h14[jj];
                    a0 += wa[4 * jj] * hv.x + wbv[4 * jj] * hw.x;
                    a1_ += wa[4 * jj + 1] * hv.y + wbv[4 * jj + 1] * hw.y;
                    a2_ += wa[4 * jj + 2] * hv.z + wbv[4 * jj + 2] * hw.z;
                    a3 += wa[4 * jj + 3] * hv.w + wbv[4 * jj + 3] * hw.w;
                }
                S->g1[r] = b1v + ((a0 + a1_) + (a2_ + a3));
            }
            if (t >= 192 && t < 192 + NN && k + 2 < BBATCH)
                cpre = vcnt[k + 2];              // optimistic pre-read, checked in phase B
        }
        __syncthreads();
        // ---- phase B: state updates + xp for k+1 + ext prefetch for k+2 ----
        if (t < 32) {
            if (k < BBATCH) {
                float gi = S->g0[t], gf = S->g0[32 + t], gg = S->g0[64 + t], go = S->g0[96 + t];
                c_ = fsig(gf) * c_ + fsig(gi) * ftanhf(gg);
                S->h0[t] = fsig(go) * ftanhf(c_);
            }
        } else if (t < 64) {
            if (k >= 1) {
                int r = t - 32;
                float gi = S->g1[r], gf = S->g1[32 + r], gg = S->g1[64 + r], go = S->g1[96 + r];
                c_ = fsig(gf) * c_ + fsig(gi) * ftanhf(gg);
                float hn = fsig(go) * ftanhf(c_);
                S->h1s[r] = hn;
                d_hseq[(((size_t)(k - 1)) * FFEAT + f) * LH + r] = hn;
            }
        } else if (t < 192) {
            if (k + 1 < BBATCH) xp_dot(S, (k + 1) & 1, t - 64);
        } else if (t < 192 + NN) {
            if (k + 2 < BBATCH) {
                if (cpre < FFEAT) {
                    while (vcnt[k + 2] < FFEAT) __nanosleep(200);
                }
                __threadfence();
                S->extn[k & 1][t - 192] =
                    __ldcg(&d_ext[((size_t)(k + 2) * FFEAT + f) * NN + (t - 192)]);
            }
        }
        __syncthreads();
    }
}

// ---------------- fused kernel ----------------
__global__ void __launch_bounds__(256) fused_kernel(const float* __restrict__ feat,
                                                    const float* __restrict__ W1g,
                                                    const float* __restrict__ Whh0,
                                                    const float* __restrict__ Wih1,
                                                    const float* __restrict__ Whh1) {
    __shared__ __align__(16) char smraw[sizeof(GatSm)];
    if (blockIdx.x >= LSTMB) {
        gat_role((GatSm*)smraw, feat, W1g, blockIdx.x - LSTMB);
    } else {
        lstm_role((LstmSm*)smraw, Whh0, Wih1, Whh1);
    }
}

// ---------------- kernel D: final FC ----------------
__global__ void __launch_bounds__(256) fc_kernel(const float* __restrict__ Wfc,
                                                 const float* __restrict__ bfc,
                                                 float* __restrict__ out) {
    int b = blockIdx.x;          // 256 blocks
    int t = threadIdx.x;
    int k = t >> 5, lane = t & 31;   // 8 warps = 8 classes
    const float* y = d_hseq + (size_t)b * (FFEAT * LH);
    const float* w = Wfc + (size_t)k * (FFEAT * LH);
    float acc = 0.f;
    for (int i = lane; i < FFEAT * LH; i += 32)
        acc += y[i] * w[i];
#pragma unroll
    for (int off = 16; off; off >>= 1)
        acc += __shfl_down_sync(0xffffffffu, acc, off);
    if (lane == 0) out[b * NC + k] = acc + bfc[k];
}

// ---------------- launch ----------------
extern "C" void kernel_launch(void* const* d_in, const int* in_sizes, int n_in,
                              void* d_out, int out_size) {
    const float* feat = (const float*)d_in[0];
    const float* W1   = (const float*)d_in[1];
    const float* a1   = (const float*)d_in[2];
    const float* W2   = (const float*)d_in[3];
    const float* a2   = (const float*)d_in[4];
    const float* Wih0 = (const float*)d_in[5];
    const float* Whh0 = (const float*)d_in[6];
    const float* bih0 = (const float*)d_in[7];
    const float* bhh0 = (const float*)d_in[8];
    const float* Wih1 = (const float*)d_in[9];
    const float* Whh1 = (const float*)d_in[10];
    const float* bih1 = (const float*)d_in[11];
    const float* bhh1 = (const float*)d_in[12];
    const float* Wfc  = (const float*)d_in[13];
    const float* bfc  = (const float*)d_in[14];
    float* out = (float*)d_out;

    prep_kernel<<<1, 256>>>(W1, a1, W2, a2, Wih0, bih0, bhh0, bih1, bhh1);
    fused_kernel<<<LSTMB + GG / WPB, 256>>>(feat, W1, Whh0, Wih1, Whh1);
    fc_kernel<<<BBATCH, 256>>>(Wfc, bfc, out);
}

// round 5
// speedup vs baseline: 1.1875x; 1.0349x over previous
#include <cuda_runtime.h>

#define NN      51
#define HIDN    64
#define HEADS   4
#define DTOT    256     // HEADS*HIDN
#define OUTG    128
#define LH      32
#define NC      8
#define BBATCH  256
#define FFEAT   50
#define GG      (BBATCH*FFEAT)   // 12800
#define SLOPEF  0.01f
#define WPB     8                // warps (graphs) per gat block
#define LSTMB   FFEAT            // lstm blocks (first in grid)

// ---------------- scratch (no allocs allowed) ----------------
__device__ float  d_u[16];               // per-head (usrc0,usrc1,udst0,udst1)
__device__ float4 d_vcomb[DTOT];         // (vs, vd, wbar, 0)
__device__ float4 d_WihT0p[NN * 32];     // packed: [n][lane] = W^T[n][lane,+32,+64,+96]
__device__ float4 d_b0p[32];             // packed b0
__device__ float  d_b1[OUTG];
__device__ float  d_xp0[GG * OUTG];      // LSTM layer0 gate pre-activations
__device__ float  d_hseq[GG * LH];       // layer1 hidden outputs
__device__ int    d_cnt[BBATCH];         // per-batch-step completion counters

// ---------------- helpers ----------------
__device__ __forceinline__ float fsig(float x) {
    return 1.0f / (1.0f + __expf(-x));
}
__device__ __forceinline__ float ftanhf(float x) {
    float e = __expf(-2.0f * fabsf(x));
    float r = __fdividef(1.0f - e, 1.0f + e);
    return copysignf(r, x);
}

// ---------------- shared-memory overlays ----------------
struct __align__(16) GatSm {
    float2 W1s[DTOT];
    float4 vcomb[DTOT];
    float  us[16];
    float2 xv[WPB][NN];
    float2 PR[WPB][HEADS][NN];
    float2 ssm[WPB][HEADS][NN];
    float4 P2z[WPB][NN];
    float2 Q2[WPB][NN];
    float  extsm[WPB][52];
};
struct __align__(16) LstmSm {
    __align__(16) float h0[LH];
    __align__(16) float h1s[LH];
    __align__(16) float g0[OUTG];
    __align__(16) float g1[OUTG];
    __align__(16) float xps[2][OUTG];    // double-buffered input projections
};

// ---------------- kernel A: precompute (32 blocks) ----------------
__global__ void prep_kernel(const float* __restrict__ W1, const float* __restrict__ a1,
                            const float* __restrict__ W2, const float* __restrict__ a2,
                            const float* __restrict__ Wih0,
                            const float* __restrict__ bih0, const float* __restrict__ bhh0,
                            const float* __restrict__ bih1, const float* __restrict__ bhh1) {
    int t = threadIdx.x; // 256 threads
    int bid = blockIdx.x;
    if (bid == 0) {
        {
            float vs = 0.f, vd = 0.f, wb = 0.f;
#pragma unroll 4
            for (int o = 0; o < OUTG; o++) {
                float w = W2[o * DTOT + t];
                vs += w * a2[o];
                vd += w * a2[OUTG + o];
                wb += w;
            }
            d_vcomb[t] = make_float4(vs, vd, wb * (1.0f / OUTG), 0.f);
        }
        if (t < 16) {
            int h = t >> 2, which = t & 3;
            int c = which & 1, side = which >> 1;
            float s = 0.f;
            for (int o = 0; o < HIDN; o++)
                s += W1[(h * HIDN + o) * 2 + c] * a1[h * 2 * HIDN + side * HIDN + o];
            d_u[t] = s;
        }
        if (t < 32)
            d_b0p[t] = make_float4(bih0[t] + bhh0[t], bih0[t + 32] + bhh0[t + 32],
                                   bih0[t + 64] + bhh0[t + 64], bih0[t + 96] + bhh0[t + 96]);
        if (t < OUTG) d_b1[t] = bih1[t] + bhh1[t];
        if (t < BBATCH) d_cnt[t] = 0;
    } else {
        // packed transpose of Wih0: 51*32 float4 items over blocks 1..31
        int idx = (bid - 1) * 256 + t;
        if (idx < NN * 32) {
            int n = idx >> 5, l = idx & 31;
            d_WihT0p[idx] = make_float4(Wih0[l * NN + n], Wih0[(l + 32) * NN + n],
                                        Wih0[(l + 64) * NN + n], Wih0[(l + 96) * NN + n]);
        }
    }
}

// ---------------- GAT role (blocks >= LSTMB) ----------------
__device__ __forceinline__ void gat_role(GatSm* S, const float* __restrict__ feat,
                                         const float* __restrict__ W1g, int gb) {
    int t = threadIdx.x, w = t >> 5, lane = t & 31;
    int g = gb * WPB + w;

    if (t < DTOT) { S->W1s[t] = ((const float2*)W1g)[t]; S->vcomb[t] = d_vcomb[t]; }
    if (t < 16) S->us[t] = d_u[t];
    {
        const float2* x2 = (const float2*)feat + (size_t)g * NN;
        for (int i = lane; i < NN; i += 32) S->xv[w][i] = x2[i];
    }
    __syncthreads();

    // stage 1: GAT1 logits + exps
    float2 q[HEADS][2];
#pragma unroll
    for (int h = 0; h < HEADS; h++) {
        float u0 = S->us[h * 4 + 0], u1 = S->us[h * 4 + 1];
        float u2 = S->us[h * 4 + 2], u3 = S->us[h * 4 + 3];
#pragma unroll
        for (int jb = 0; jb < 2; jb++) {
            int j = jb * 32 + lane;
            float2 xn = (j < NN) ? S->xv[w][j] : make_float2(0.f, 0.f);
            float es = xn.x * u0 + xn.y * u1;
            float ed = xn.x * u2 + xn.y * u3;
            if (j < NN) S->PR[w][h][j] = make_float2(__expf(es), __expf(SLOPEF * es));
            q[h][jb] = make_float2(__expf(ed), __expf(SLOPEF * ed));
        }
    }
    __syncwarp();

    // stage 2: attention-weighted feature sums
#pragma unroll
    for (int h = 0; h < HEADS; h++) {
        float2 q0 = q[h][0], q1 = q[h][1];
        float den0 = 0.f, s00 = 0.f, s01 = 0.f;
        float den1 = 0.f, s10 = 0.f, s11 = 0.f;
#pragma unroll 3
        for (int i = 0; i < NN; i++) {
            float2 pr = S->PR[w][h][i];
            float2 xi = S->xv[w][i];
            float w0 = fmaxf(pr.x * q0.x, pr.y * q0.y);
            float w1 = fmaxf(pr.x * q1.x, pr.y * q1.y);
            den0 += w0; s00 += w0 * xi.x; s01 += w0 * xi.y;
            den1 += w1; s10 += w1 * xi.x; s11 += w1 * xi.y;
        }
        {
            int j0 = lane;
            float2 pr = S->PR[w][h][j0]; float2 xj = S->xv[w][j0];
            float w0 = fmaxf(pr.x * q0.x, pr.y * q0.y);
            den0 -= w0; s00 -= w0 * xj.x; s01 -= w0 * xj.y;
            float inv = __fdividef(1.0f, den0);
            S->ssm[w][h][j0] = make_float2(s00 * inv, s01 * inv);
        }
        int j1 = 32 + lane;
        if (j1 < NN) {
            float2 pr = S->PR[w][h][j1]; float2 xj = S->xv[w][j1];
            float w1 = fmaxf(pr.x * q1.x, pr.y * q1.y);
            den1 -= w1; s10 -= w1 * xj.x; s11 -= w1 * xj.y;
            float inv = __fdividef(1.0f, den1);
            S->ssm[w][h][j1] = make_float2(s10 * inv, s11 * inv);
        }
    }
    __syncwarp();

    // stage 3: elu(h1) projections -> es2, ed2, zbar
    {
        int grp = lane >> 3, gl = lane & 7;
#pragma unroll 1
        for (int p = 0; p < 13; p++) {
            int j = p * 4 + grp;
            bool valid = (j < NN);
            int jc = valid ? j : 0;
            float2 sh[HEADS];
#pragma unroll
            for (int h = 0; h < HEADS; h++) sh[h] = S->ssm[w][h][jc];
            float a_es = 0.f, a_ed = 0.f, a_zb = 0.f;
#pragma unroll
            for (int h = 0; h < HEADS; h++) {
                float sx = sh[h].x, sy = sh[h].y;
#pragma unroll
                for (int kk = 0; kk < 8; kk++) {
                    int d = h * 64 + kk * 8 + gl;
                    float2 wv = S->W1s[d];
                    float h1 = sx * wv.x + sy * wv.y;
                    float he = (h1 > 0.f) ? h1 : (__expf(h1) - 1.0f);
                    float4 vc = S->vcomb[d];
                    a_es += he * vc.x; a_ed += he * vc.y; a_zb += he * vc.z;
                }
            }
#pragma unroll
            for (int off = 4; off; off >>= 1) {
                a_es += __shfl_down_sync(0xffffffffu, a_es, off);
                a_ed += __shfl_down_sync(0xffffffffu, a_ed, off);
                a_zb += __shfl_down_sync(0xffffffffu, a_zb, off);
            }
            if (gl == 0 && valid) {
                S->P2z[w][j] = make_float4(__expf(a_es), __expf(SLOPEF * a_es), a_zb, 0.f);
                S->Q2[w][j] = make_float2(__expf(a_ed), __expf(SLOPEF * a_ed));
            }
        }
    }
    __syncwarp();

    // stage 5: GAT2 attention -> extracted (into smem)
#pragma unroll
    for (int jb = 0; jb < 2; jb++) {
        int j = jb * 32 + lane;
        if (j < NN) {
            float2 qq = S->Q2[w][j];
            float den = 0.f, acc = 0.f;
#pragma unroll 3
            for (int i = 0; i < NN; i++) {
                float4 p = S->P2z[w][i];
                float w_ = fmaxf(p.x * qq.x, p.y * qq.y);
                den += w_; acc += w_ * p.z;
            }
            float4 p = S->P2z[w][j];
            float w_ = fmaxf(p.x * qq.x, p.y * qq.y);
            den -= w_; acc -= w_ * p.z;
            S->extsm[w][j] = acc * __fdividef(1.0f, den);
        }
    }
    __syncwarp();

    // stage 6: xp0 = ext @ WihT0 + b0 (per-lane 4 cols), publish counter
    {
        float4 acc = d_b0p[lane];
#pragma unroll 4
        for (int n = 0; n < NN; n++) {
            float e = S->extsm[w][n];
            float4 wv = __ldg(&d_WihT0p[n * 32 + lane]);
            acc.x += e * wv.x; acc.y += e * wv.y;
            acc.z += e * wv.z; acc.w += e * wv.w;
        }
        float* xg = d_xp0 + (size_t)g * OUTG;
        xg[lane] = acc.x; xg[lane + 32] = acc.y;
        xg[lane + 64] = acc.z; xg[lane + 96] = acc.w;
    }
    __threadfence();
    if (lane == 0) atomicAdd(&d_cnt[g / FFEAT], 1);
}

// ---------------- LSTM role (blocks < LSTMB) ----------------
__device__ __forceinline__ void lstm_role(LstmSm* S,
                                          const float* __restrict__ Whh0,
                                          const float* __restrict__ Wih1,
                                          const float* __restrict__ Whh1) {
    int f = blockIdx.x;
    int t = threadIdx.x;

    float wa[32], wbv[32];
    if (t < OUTG) {
#pragma unroll
        for (int k = 0; k < 32; k++) wa[k] = Whh0[t * 32 + k];
    } else {
        int r = t - OUTG;
#pragma unroll
        for (int k = 0; k < 32; k++) { wa[k] = Wih1[r * 32 + k]; wbv[k] = Whh1[r * 32 + k]; }
    }
    float b1v = (t >= OUTG) ? d_b1[t - OUTG] : 0.f;
    float c_ = 0.f;
    if (t < LH) { S->h0[t] = 0.f; S->h1s[t] = 0.f; }
    volatile int* vcnt = d_cnt;

    // prologue: xp for steps 0,1 into smem; step 2 into pipeline register
    if (t < OUTG) {
        while (vcnt[0] < FFEAT) __nanosleep(200);
        __threadfence();
        S->xps[0][t] = __ldcg(&d_xp0[(size_t)f * OUTG + t]);
        while (vcnt[1] < FFEAT) __nanosleep(200);
        __threadfence();
        S->xps[1][t] = __ldcg(&d_xp0[((size_t)FFEAT + f) * OUTG + t]);
    }
    float ldreg = 0.f;
    if (t >= 64 && t < 192) {
        while (vcnt[2] < FFEAT) __nanosleep(200);
        __threadfence();
        ldreg = __ldcg(&d_xp0[((size_t)2 * FFEAT + f) * OUTG + (t - 64)]);
    }
    __syncthreads();

    for (int k = 0; k <= BBATCH; k++) {
        // ---- phase A: gate dots (layer0 @ k, layer1 @ k-1) ----
        if (t < OUTG) {
            if (k < BBATCH) {
                const float4* h4 = (const float4*)S->h0;
                float xpv = S->xps[k & 1][t];
                float a0 = 0.f, a1_ = 0.f, a2_ = 0.f, a3 = 0.f;
#pragma unroll
                for (int jj = 0; jj < 8; jj++) {
                    float4 hv = h4[jj];
                    a0 += wa[4 * jj] * hv.x;
                    a1_ += wa[4 * jj + 1] * hv.y;
                    a2_ += wa[4 * jj + 2] * hv.z;
                    a3 += wa[4 * jj + 3] * hv.w;
                }
                S->g0[t] = xpv + ((a0 + a1_) + (a2_ + a3));
            }
        } else if (k >= 1) {
            int r = t - OUTG;
            const float4* h4 = (const float4*)S->h0;
            const float4* h14 = (const float4*)S->h1s;
            float a0 = 0.f, a1_ = 0.f, a2_ = 0.f, a3 = 0.f;
#pragma unroll
            for (int jj = 0; jj < 8; jj++) {
                float4 hv = h4[jj]; float4 hw = h14[jj];
                a0 += wa[4 * jj] * hv.x + wbv[4 * jj] * hw.x;
                a1_ += wa[4 * jj + 1] * hv.y + wbv[4 * jj + 1] * hw.y;
                a2_ += wa[4 * jj + 2] * hv.z + wbv[4 * jj + 2] * hw.z;
                a3 += wa[4 * jj + 3] * hv.w + wbv[4 * jj + 3] * hw.w;
            }
            S->g1[r] = b1v + ((a0 + a1_) + (a2_ + a3));
        }
        __syncthreads();
        // ---- phase B: state updates + xp prefetch pipeline ----
        if (t < 32) {
            if (k < BBATCH) {
                float gi = S->g0[t], gf = S->g0[32 + t], gg = S->g0[64 + t], go = S->g0[96 + t];
                c_ = fsig(gf) * c_ + fsig(gi) * ftanhf(gg);
                S->h0[t] = fsig(go) * ftanhf(c_);
            }
        } else if (t < 64) {
            if (k >= 1) {
                int r = t - 32;
                float gi = S->g1[r], gf = S->g1[32 + r], gg = S->g1[64 + r], go = S->g1[96 + r];
                c_ = fsig(gf) * c_ + fsig(gi) * ftanhf(gg);
                float hn = fsig(go) * ftanhf(c_);
                S->h1s[r] = hn;
                d_hseq[(((size_t)(k - 1)) * FFEAT + f) * LH + r] = hn;
            }
        } else if (t < 192) {
            int col = t - 64;
            if (k + 2 < BBATCH) S->xps[k & 1][col] = ldreg;   // xp for step k+2
            if (k + 3 < BBATCH) {
                while (vcnt[k + 3] < FFEAT) __nanosleep(200);
                __threadfence();
                ldreg = __ldcg(&d_xp0[((size_t)(k + 3) * FFEAT + f) * OUTG + col]);
            }
        }
        __syncthreads();
    }
}

// ---------------- fused kernel ----------------
__global__ void __launch_bounds__(256) fused_kernel(const float* __restrict__ feat,
                                                    const float* __restrict__ W1g,
                                                    const float* __restrict__ Whh0,
                                                    const float* __restrict__ Wih1,
                                                    const float* __restrict__ Whh1) {
    __shared__ __align__(16) char smraw[sizeof(GatSm)];
    if (blockIdx.x >= LSTMB) {
        gat_role((GatSm*)smraw, feat, W1g, blockIdx.x - LSTMB);
    } else {
        lstm_role((LstmSm*)smraw, Whh0, Wih1, Whh1);
    }
}

// ---------------- kernel D: final FC ----------------
__global__ void __launch_bounds__(256) fc_kernel(const float* __restrict__ Wfc,
                                                 const float* __restrict__ bfc,
                                                 float* __restrict__ out) {
    int b = blockIdx.x;          // 256 blocks
    int t = threadIdx.x;
    int k = t >> 5, lane = t & 31;   // 8 warps = 8 classes
    const float* y = d_hseq + (size_t)b * (FFEAT * LH);
    const float* w = Wfc + (size_t)k * (FFEAT * LH);
    float acc = 0.f;
    for (int i = lane; i < FFEAT * LH; i += 32)
        acc += y[i] * w[i];
#pragma unroll
    for (int off = 16; off; off >>= 1)
        acc += __shfl_down_sync(0xffffffffu, acc, off);
    if (lane == 0) out[b * NC + k] = acc + bfc[k];
}

// ---------------- launch ----------------
extern "C" void kernel_launch(void* const* d_in, const int* in_sizes, int n_in,
                              void* d_out, int out_size) {
    const float* feat = (const float*)d_in[0];
    const float* W1   = (const float*)d_in[1];
    const float* a1   = (const float*)d_in[2];
    const float* W2   = (const float*)d_in[3];
    const float* a2   = (const float*)d_in[4];
    const float* Wih0 = (const float*)d_in[5];
    const float* Whh0 = (const float*)d_in[6];
    const float* bih0 = (const float*)d_in[7];
    const float* bhh0 = (const float*)d_in[8];
    const float* Wih1 = (const float*)d_in[9];
    const float* Whh1 = (const float*)d_in[10];
    const float* bih1 = (const float*)d_in[11];
    const float* bhh1 = (const float*)d_in[12];
    const float* Wfc  = (const float*)d_in[13];
    const float* bfc  = (const float*)d_in[14];
    float* out = (float*)d_out;

    prep_kernel<<<32, 256>>>(W1, a1, W2, a2, Wih0, bih0, bhh0, bih1, bhh1);
    fused_kernel<<<LSTMB + GG / WPB, 256>>>(feat, W1, Whh0, Wih1, Whh1);
    fc_kernel<<<BBATCH, 256>>>(Wfc, bfc, out);
}